// round 3
// baseline (speedup 1.0000x reference)
#include <cuda_runtime.h>
#include <math.h>

// Problem constants
#define NB 4
#define NQ 2048
#define NK 2048
#define ND 1024

// 67 MB scratch for scores/probabilities [B, Q, K]
__device__ static float g_scores[(size_t)NB * NQ * NK];

// ----------------------------------------------------------------------------
// GEMM1 (NT): S[b,m,n] = sum_k Q[b,m,k] * V[b,n,k]
// M=2048, N=2048, Kd=1024. Tiles 128x128x16, 256 threads, 8x8 per thread.
// ----------------------------------------------------------------------------
__global__ __launch_bounds__(256, 2)
void gemm_qk_kernel(const float* __restrict__ Qg, const float* __restrict__ Vg)
{
    const int M = NQ, N = NK, Kd = ND;
    const int b = blockIdx.z;
    const float* A = Qg + (size_t)b * M * Kd;
    const float* B = Vg + (size_t)b * N * Kd;
    float*       C = g_scores + (size_t)b * M * N;

    const int m0 = blockIdx.y * 128;
    const int n0 = blockIdx.x * 128;

    __shared__ float As[16][128];
    __shared__ float Bs[16][128];

    const int tid = threadIdx.x;
    const int tx = tid & 15;          // n direction (0..15)
    const int ty = tid >> 4;          // m direction (0..15)

    float acc[8][8];
    #pragma unroll
    for (int i = 0; i < 8; i++)
        #pragma unroll
        for (int j = 0; j < 8; j++) acc[i][j] = 0.0f;

    for (int k0 = 0; k0 < Kd; k0 += 16) {
        // Load A tile (128 rows x 16 cols) transposed into As[k][m]
        // and B tile (128 rows x 16 cols) transposed into Bs[k][n].
        #pragma unroll
        for (int r = 0; r < 2; r++) {
            int idx  = tid + r * 256;      // 0..511
            int row  = idx >> 2;           // 0..127
            int colv = idx & 3;            // 0..3 (float4 index)
            float4 va = *(const float4*)(A + (size_t)(m0 + row) * Kd + k0 + colv * 4);
            As[colv * 4 + 0][row] = va.x;
            As[colv * 4 + 1][row] = va.y;
            As[colv * 4 + 2][row] = va.z;
            As[colv * 4 + 3][row] = va.w;
            float4 vb = *(const float4*)(B + (size_t)(n0 + row) * Kd + k0 + colv * 4);
            Bs[colv * 4 + 0][row] = vb.x;
            Bs[colv * 4 + 1][row] = vb.y;
            Bs[colv * 4 + 2][row] = vb.z;
            Bs[colv * 4 + 3][row] = vb.w;
        }
        __syncthreads();

        #pragma unroll
        for (int kk = 0; kk < 16; kk++) {
            float af[8], bf[8];
            #pragma unroll
            for (int i = 0; i < 8; i++) af[i] = As[kk][ty * 8 + i];
            #pragma unroll
            for (int j = 0; j < 8; j++) bf[j] = Bs[kk][tx * 8 + j];
            #pragma unroll
            for (int i = 0; i < 8; i++)
                #pragma unroll
                for (int j = 0; j < 8; j++)
                    acc[i][j] = fmaf(af[i], bf[j], acc[i][j]);
        }
        __syncthreads();
    }

    #pragma unroll
    for (int i = 0; i < 8; i++) {
        float* crow = C + (size_t)(m0 + ty * 8 + i) * N + n0 + tx * 8;
        float4 c0 = make_float4(acc[i][0], acc[i][1], acc[i][2], acc[i][3]);
        float4 c1 = make_float4(acc[i][4], acc[i][5], acc[i][6], acc[i][7]);
        *(float4*)(crow + 0) = c0;
        *(float4*)(crow + 4) = c1;
    }
}

// ----------------------------------------------------------------------------
// Row softmax over the last dim (2048) of g_scores, in place.
// One block (256 threads) per row; 8 elements per thread.
// ----------------------------------------------------------------------------
__global__ __launch_bounds__(256)
void softmax_kernel()
{
    const size_t row = blockIdx.x;                       // 0 .. NB*NQ-1
    float* p = g_scores + row * (size_t)NK;
    float4* p4 = (float4*)p;
    const int tid  = threadIdx.x;
    const int lane = tid & 31;
    const int warp = tid >> 5;

    __shared__ float red[8];

    float4 v0 = p4[tid];
    float4 v1 = p4[tid + 256];

    // --- max reduce ---
    float m = fmaxf(fmaxf(fmaxf(v0.x, v0.y), fmaxf(v0.z, v0.w)),
                    fmaxf(fmaxf(v1.x, v1.y), fmaxf(v1.z, v1.w)));
    #pragma unroll
    for (int off = 16; off > 0; off >>= 1)
        m = fmaxf(m, __shfl_xor_sync(0xffffffffu, m, off));
    if (lane == 0) red[warp] = m;
    __syncthreads();
    float rowmax = red[0];
    #pragma unroll
    for (int w = 1; w < 8; w++) rowmax = fmaxf(rowmax, red[w]);
    __syncthreads();

    // --- exp + sum reduce ---
    v0.x = expf(v0.x - rowmax); v0.y = expf(v0.y - rowmax);
    v0.z = expf(v0.z - rowmax); v0.w = expf(v0.w - rowmax);
    v1.x = expf(v1.x - rowmax); v1.y = expf(v1.y - rowmax);
    v1.z = expf(v1.z - rowmax); v1.w = expf(v1.w - rowmax);

    float s = (v0.x + v0.y + v0.z + v0.w) + (v1.x + v1.y + v1.z + v1.w);
    #pragma unroll
    for (int off = 16; off > 0; off >>= 1)
        s += __shfl_xor_sync(0xffffffffu, s, off);
    if (lane == 0) red[warp] = s;
    __syncthreads();
    float rowsum = 0.0f;
    #pragma unroll
    for (int w = 0; w < 8; w++) rowsum += red[w];

    const float inv = 1.0f / rowsum;
    v0.x *= inv; v0.y *= inv; v0.z *= inv; v0.w *= inv;
    v1.x *= inv; v1.y *= inv; v1.z *= inv; v1.w *= inv;
    p4[tid]       = v0;
    p4[tid + 256] = v1;
}

// ----------------------------------------------------------------------------
// GEMM2 (NN): O[b,m,n] = sum_k P[b,m,k] * V[b,k,n]
// M=2048, N=1024, Kd=2048. Tiles 128x128x16, 256 threads, 8x8 per thread.
// ----------------------------------------------------------------------------
__global__ __launch_bounds__(256, 2)
void gemm_pv_kernel(const float* __restrict__ Vg, float* __restrict__ Og)
{
    const int M = NQ, N = ND, Kd = NK;
    const int b = blockIdx.z;
    const float* A = g_scores + (size_t)b * M * Kd;   // P, row-major [M, Kd]
    const float* B = Vg + (size_t)b * Kd * N;          // V, row-major [Kd, N]
    float*       C = Og + (size_t)b * M * N;

    const int m0 = blockIdx.y * 128;
    const int n0 = blockIdx.x * 128;

    __shared__ float As[16][128];
    __shared__ float Bs[16][128];

    const int tid = threadIdx.x;
    const int tx = tid & 15;
    const int ty = tid >> 4;

    float acc[8][8];
    #pragma unroll
    for (int i = 0; i < 8; i++)
        #pragma unroll
        for (int j = 0; j < 8; j++) acc[i][j] = 0.0f;

    for (int k0 = 0; k0 < Kd; k0 += 16) {
        // A tile: 128 rows x 16 cols, transposed into As[k][m]
        #pragma unroll
        for (int r = 0; r < 2; r++) {
            int idx  = tid + r * 256;
            int row  = idx >> 2;
            int colv = idx & 3;
            float4 va = *(const float4*)(A + (size_t)(m0 + row) * Kd + k0 + colv * 4);
            As[colv * 4 + 0][row] = va.x;
            As[colv * 4 + 1][row] = va.y;
            As[colv * 4 + 2][row] = va.z;
            As[colv * 4 + 3][row] = va.w;
        }
        // B tile: 16 rows x 128 cols, direct into Bs[k][n] (coalesced)
        #pragma unroll
        for (int r = 0; r < 2; r++) {
            int idx  = tid + r * 256;      // 0..511
            int row  = idx >> 5;           // 0..15
            int colv = idx & 31;           // 0..31
            float4 vb = *(const float4*)(B + (size_t)(k0 + row) * N + n0 + colv * 4);
            *(float4*)&Bs[row][colv * 4] = vb;
        }
        __syncthreads();

        #pragma unroll
        for (int kk = 0; kk < 16; kk++) {
            float af[8], bf[8];
            #pragma unroll
            for (int i = 0; i < 8; i++) af[i] = As[kk][ty * 8 + i];
            #pragma unroll
            for (int j = 0; j < 8; j++) bf[j] = Bs[kk][tx * 8 + j];
            #pragma unroll
            for (int i = 0; i < 8; i++)
                #pragma unroll
                for (int j = 0; j < 8; j++)
                    acc[i][j] = fmaf(af[i], bf[j], acc[i][j]);
        }
        __syncthreads();
    }

    #pragma unroll
    for (int i = 0; i < 8; i++) {
        float* crow = C + (size_t)(m0 + ty * 8 + i) * N + n0 + tx * 8;
        float4 c0 = make_float4(acc[i][0], acc[i][1], acc[i][2], acc[i][3]);
        float4 c1 = make_float4(acc[i][4], acc[i][5], acc[i][6], acc[i][7]);
        *(float4*)(crow + 0) = c0;
        *(float4*)(crow + 4) = c1;
    }
}

// ----------------------------------------------------------------------------
extern "C" void kernel_launch(void* const* d_in, const int* in_sizes, int n_in,
                              void* d_out, int out_size)
{
    const float* q = (const float*)d_in[0];   // [4, 2048, 1024]
    const float* v = (const float*)d_in[1];   // [4, 2048, 1024]
    float* out = (float*)d_out;               // [4, 2048, 1024]

    // S = Q @ V^T
    {
        dim3 grid(NK / 128, NQ / 128, NB);    // (16, 16, 4)
        gemm_qk_kernel<<<grid, 256>>>(q, v);
    }
    // P = softmax(S) rowwise, in place
    {
        softmax_kernel<<<NB * NQ, 256>>>();
    }
    // O = P @ V
    {
        dim3 grid(ND / 128, NQ / 128, NB);    // (8, 16, 4)
        gemm_pv_kernel<<<grid, 256>>>(v, out);
    }
}

// round 7
// speedup vs baseline: 2.4125x; 2.4125x over previous
#include <cuda_runtime.h>
#include <cuda_bf16.h>
#include <cstdint>
#include <math.h>

// Problem constants
#define NB 4
#define NQ 2048
#define NK 2048
#define ND 1024

// ---------------------------------------------------------------------------
// Device scratch (static __device__ arrays; allocation-free rule)
// ---------------------------------------------------------------------------
__device__ static float g_scores[(size_t)NB * NQ * NK];                    // 67 MB
__device__ static __nv_bfloat16 g_qhi[(size_t)NB * NQ * ND];
__device__ static __nv_bfloat16 g_qlo[(size_t)NB * NQ * ND];
__device__ static __nv_bfloat16 g_vhi[(size_t)NB * NK * ND];
__device__ static __nv_bfloat16 g_vlo[(size_t)NB * NK * ND];
__device__ static __nv_bfloat16 g_vthi[(size_t)NB * ND * NK];              // V^T
__device__ static __nv_bfloat16 g_vtlo[(size_t)NB * ND * NK];
__device__ static __nv_bfloat16 g_phi[(size_t)NB * NQ * NK];
__device__ static __nv_bfloat16 g_plo[(size_t)NB * NQ * NK];

// ---------------------------------------------------------------------------
// hi/lo split helpers
// ---------------------------------------------------------------------------
__device__ __forceinline__ void split1(float x, __nv_bfloat16& h, __nv_bfloat16& l) {
    h = __float2bfloat16(x);
    l = __float2bfloat16(x - __bfloat162float(h));
}

__device__ __forceinline__ void split_store4(__nv_bfloat16* hp, __nv_bfloat16* lp, float4 v) {
    __nv_bfloat16 h0, h1, h2, h3, l0, l1, l2, l3;
    split1(v.x, h0, l0); split1(v.y, h1, l1);
    split1(v.z, h2, l2); split1(v.w, h3, l3);
    __nv_bfloat162 ha; ha.x = h0; ha.y = h1;
    __nv_bfloat162 hb; hb.x = h2; hb.y = h3;
    __nv_bfloat162 la; la.x = l0; la.y = l1;
    __nv_bfloat162 lb; lb.x = l2; lb.y = l3;
    *(__nv_bfloat162*)(hp)     = ha;
    *(__nv_bfloat162*)(hp + 2) = hb;
    *(__nv_bfloat162*)(lp)     = la;
    *(__nv_bfloat162*)(lp + 2) = lb;
}

// ---------------------------------------------------------------------------
// Elementwise split: fp32 -> (hi, lo) bf16
// ---------------------------------------------------------------------------
__global__ __launch_bounds__(256)
void split_kernel(const float4* __restrict__ in, __nv_bfloat16* __restrict__ hi,
                  __nv_bfloat16* __restrict__ lo) {
    int i = blockIdx.x * 256 + threadIdx.x;
    float4 v = in[i];
    split_store4(hi + (size_t)i * 4, lo + (size_t)i * 4, v);
}

// ---------------------------------------------------------------------------
// Transpose + split: V[b,k,d] fp32 -> Vt_hi/lo[b,d,k] bf16
// ---------------------------------------------------------------------------
__global__ __launch_bounds__(256)
void transpose_split_kernel(const float* __restrict__ V,
                            __nv_bfloat16* __restrict__ vthi,
                            __nv_bfloat16* __restrict__ vtlo) {
    __shared__ float tile[32][33];
    const int b = blockIdx.z;
    const int k0 = blockIdx.y * 32;
    const int d0 = blockIdx.x * 32;
    const int tx = threadIdx.x & 31;
    const int ty = threadIdx.x >> 5;   // 0..7
    const float* Vb = V + (size_t)b * NK * ND;

    #pragma unroll
    for (int r = ty; r < 32; r += 8)
        tile[r][tx] = Vb[(size_t)(k0 + r) * ND + d0 + tx];
    __syncthreads();

    __nv_bfloat16* H = vthi + (size_t)b * ND * NK;
    __nv_bfloat16* L = vtlo + (size_t)b * ND * NK;
    #pragma unroll
    for (int r = ty; r < 32; r += 8) {
        float x = tile[tx][r];
        __nv_bfloat16 h, l;
        split1(x, h, l);
        size_t o = (size_t)(d0 + r) * NK + k0 + tx;
        H[o] = h;
        L[o] = l;
    }
}

// ---------------------------------------------------------------------------
// Row softmax over g_scores (last dim 2048), fused hi/lo split output.
// ---------------------------------------------------------------------------
__global__ __launch_bounds__(256)
void softmax_split_kernel(__nv_bfloat16* __restrict__ phi,
                          __nv_bfloat16* __restrict__ plo) {
    const size_t row = blockIdx.x;
    float* p = g_scores + row * (size_t)NK;
    float4* p4 = (float4*)p;
    const int tid = threadIdx.x;
    const int lane = tid & 31;
    const int warp = tid >> 5;

    __shared__ float red[8];

    float4 v0 = p4[tid];
    float4 v1 = p4[tid + 256];

    float m = fmaxf(fmaxf(fmaxf(v0.x, v0.y), fmaxf(v0.z, v0.w)),
                    fmaxf(fmaxf(v1.x, v1.y), fmaxf(v1.z, v1.w)));
    #pragma unroll
    for (int off = 16; off > 0; off >>= 1)
        m = fmaxf(m, __shfl_xor_sync(0xffffffffu, m, off));
    if (lane == 0) red[warp] = m;
    __syncthreads();
    float rowmax = red[0];
    #pragma unroll
    for (int w = 1; w < 8; w++) rowmax = fmaxf(rowmax, red[w]);
    __syncthreads();

    v0.x = expf(v0.x - rowmax); v0.y = expf(v0.y - rowmax);
    v0.z = expf(v0.z - rowmax); v0.w = expf(v0.w - rowmax);
    v1.x = expf(v1.x - rowmax); v1.y = expf(v1.y - rowmax);
    v1.z = expf(v1.z - rowmax); v1.w = expf(v1.w - rowmax);

    float s = (v0.x + v0.y + v0.z + v0.w) + (v1.x + v1.y + v1.z + v1.w);
    #pragma unroll
    for (int off = 16; off > 0; off >>= 1)
        s += __shfl_xor_sync(0xffffffffu, s, off);
    if (lane == 0) red[warp] = s;
    __syncthreads();
    float rowsum = 0.0f;
    #pragma unroll
    for (int w = 0; w < 8; w++) rowsum += red[w];

    const float inv = 1.0f / rowsum;
    v0.x *= inv; v0.y *= inv; v0.z *= inv; v0.w *= inv;
    v1.x *= inv; v1.y *= inv; v1.z *= inv; v1.w *= inv;

    __nv_bfloat16* H = phi + row * (size_t)NK;
    __nv_bfloat16* L = plo + row * (size_t)NK;
    split_store4(H + 4 * tid,         L + 4 * tid,         v0);
    split_store4(H + 4 * (tid + 256), L + 4 * (tid + 256), v1);
}

// ---------------------------------------------------------------------------
// HMMA (mma.sync m16n8k16 bf16) split GEMM:
//   C[b,m,n] = sum_k (Ahi+Alo)[b,m,k] * (Bhi+Blo)[b,n,k]   (3-pass: hh+hl+lh)
// CTA tile 128x128, K chunk 32, 8 warps (4 m x 2 n), warp tile 32x64.
// cp.async double-buffered smem; fragments read directly from padded smem.
// ---------------------------------------------------------------------------
#define KCH 32                 // k per chunk (bf16 elems)
#define SROW 40                // padded smem row stride in bf16 elems (80 B)
#define TILE_E (128 * SROW)    // 5120 elems per operand tile
#define STAGE_E (4 * TILE_E)   // 20480 elems per stage (40960 B)
#define SMEM_BYTES (2 * STAGE_E * 2)   // 81920 B

__device__ __forceinline__ void mma_bf16(float* d, const uint32_t* a, const uint32_t* b) {
    asm volatile(
        "mma.sync.aligned.m16n8k16.row.col.f32.bf16.bf16.f32 "
        "{%0,%1,%2,%3}, {%4,%5,%6,%7}, {%8,%9}, {%0,%1,%2,%3};"
        : "+f"(d[0]), "+f"(d[1]), "+f"(d[2]), "+f"(d[3])
        : "r"(a[0]), "r"(a[1]), "r"(a[2]), "r"(a[3]), "r"(b[0]), "r"(b[1]));
}

__device__ __forceinline__ void cp_async16(void* sdst, const void* gsrc) {
    uint32_t s;
    asm("{ .reg .u64 t; cvta.to.shared.u64 t, %1; cvt.u32.u64 %0, t; }"
        : "=r"(s) : "l"(sdst));
    asm volatile("cp.async.cg.shared.global [%0], [%1], 16;" :: "r"(s), "l"(gsrc));
}

__global__ __launch_bounds__(256, 1)
void hmma_gemm_kernel(const __nv_bfloat16* __restrict__ Ahi,
                      const __nv_bfloat16* __restrict__ Alo,
                      const __nv_bfloat16* __restrict__ Bhi,
                      const __nv_bfloat16* __restrict__ Blo,
                      float* __restrict__ C,
                      int Kd, int N) {
    extern __shared__ __nv_bfloat16 sm[];
    const int tid = threadIdx.x;
    const int wid = tid >> 5;
    const int lane = tid & 31;
    const int group = lane >> 2;       // 0..7
    const int tig = lane & 3;          // 0..3
    const int b = blockIdx.z;
    const int m0 = blockIdx.y * 128;
    const int n0 = blockIdx.x * 128;
    const int wm = (wid & 3) * 32;     // warp row base within tile
    const int wn = (wid >> 2) * 64;    // warp col base within tile

    const __nv_bfloat16* srcs[4];
    srcs[0] = Ahi + (size_t)b * 2048 * Kd;
    srcs[1] = Alo + (size_t)b * 2048 * Kd;
    srcs[2] = Bhi + (size_t)b * (size_t)N * Kd;
    srcs[3] = Blo + (size_t)b * (size_t)N * Kd;

    float acc[2][8][4];
    #pragma unroll
    for (int i = 0; i < 2; i++)
        #pragma unroll
        for (int j = 0; j < 8; j++)
            #pragma unroll
            for (int r = 0; r < 4; r++) acc[i][j][r] = 0.0f;

    const int nch = Kd / KCH;

    // --- chunk loader: 8 x cp.async 16B per thread ---
    auto load_chunk = [&](int ci) {
        const int k0 = ci * KCH;
        __nv_bfloat16* st = sm + (ci & 1) * STAGE_E;
        #pragma unroll
        for (int T = 0; T < 4; ++T) {
            const __nv_bfloat16* src = srcs[T];
            const int r0 = (T < 2) ? m0 : n0;
            #pragma unroll
            for (int j = 0; j < 2; ++j) {
                int idx = tid + j * 256;       // 0..511
                int row = idx >> 2;            // 0..127
                int c   = idx & 3;             // 16B column
                cp_async16(st + T * TILE_E + row * SROW + c * 8,
                           src + (size_t)(r0 + row) * Kd + k0 + c * 8);
            }
        }
        asm volatile("cp.async.commit_group;" ::: "memory");
    };

    load_chunk(0);

    for (int i = 0; i < nch; ++i) {
        if (i + 1 < nch) {
            load_chunk(i + 1);
            asm volatile("cp.async.wait_group 1;" ::: "memory");
        } else {
            asm volatile("cp.async.wait_group 0;" ::: "memory");
        }
        __syncthreads();

        const __nv_bfloat16* st = sm + (i & 1) * STAGE_E;
        const __nv_bfloat16* sAh = st;
        const __nv_bfloat16* sAl = st + TILE_E;
        const __nv_bfloat16* sBh = st + 2 * TILE_E;
        const __nv_bfloat16* sBl = st + 3 * TILE_E;

        #pragma unroll
        for (int ks = 0; ks < 2; ++ks) {
            const int kb = ks * 16 + 2 * tig;   // lane k offset within chunk

            // A fragments: 2 m-tiles x {hi, lo} x 4 regs
            uint32_t ah[2][4], al[2][4];
            #pragma unroll
            for (int mt = 0; mt < 2; ++mt) {
                const int ar = wm + mt * 16 + group;
                ah[mt][0] = *(const uint32_t*)(sAh + ar * SROW + kb);
                ah[mt][1] = *(const uint32_t*)(sAh + (ar + 8) * SROW + kb);
                ah[mt][2] = *(const uint32_t*)(sAh + ar * SROW + kb + 8);
                ah[mt][3] = *(const uint32_t*)(sAh + (ar + 8) * SROW + kb + 8);
                al[mt][0] = *(const uint32_t*)(sAl + ar * SROW + kb);
                al[mt][1] = *(const uint32_t*)(sAl + (ar + 8) * SROW + kb);
                al[mt][2] = *(const uint32_t*)(sAl + ar * SROW + kb + 8);
                al[mt][3] = *(const uint32_t*)(sAl + (ar + 8) * SROW + kb + 8);
            }

            #pragma unroll
            for (int nt = 0; nt < 8; ++nt) {
                const int br = wn + nt * 8 + group;
                uint32_t bh[2], bl[2];
                bh[0] = *(const uint32_t*)(sBh + br * SROW + kb);
                bh[1] = *(const uint32_t*)(sBh + br * SROW + kb + 8);
                bl[0] = *(const uint32_t*)(sBl + br * SROW + kb);
                bl[1] = *(const uint32_t*)(sBl + br * SROW + kb + 8);
                #pragma unroll
                for (int mt = 0; mt < 2; ++mt) {
                    mma_bf16(acc[mt][nt], ah[mt], bh);   // hi*hi
                    mma_bf16(acc[mt][nt], ah[mt], bl);   // hi*lo
                    mma_bf16(acc[mt][nt], al[mt], bh);   // lo*hi
                }
            }
        }
        __syncthreads();
    }

    // Epilogue: direct float2 stores
    float* Cb = C + (size_t)b * 2048 * (size_t)N;
    #pragma unroll
    for (int mt = 0; mt < 2; ++mt) {
        const int row = m0 + wm + mt * 16 + group;
        #pragma unroll
        for (int nt = 0; nt < 8; ++nt) {
            const int col = n0 + wn + nt * 8 + 2 * tig;
            float2 lo2, hi2;
            lo2.x = acc[mt][nt][0]; lo2.y = acc[mt][nt][1];
            hi2.x = acc[mt][nt][2]; hi2.y = acc[mt][nt][3];
            *(float2*)(Cb + (size_t)row * N + col)       = lo2;
            *(float2*)(Cb + (size_t)(row + 8) * N + col) = hi2;
        }
    }
}

// ---------------------------------------------------------------------------
extern "C" void kernel_launch(void* const* d_in, const int* in_sizes, int n_in,
                              void* d_out, int out_size) {
    const float* q = (const float*)d_in[0];   // [4, 2048, 1024]
    const float* v = (const float*)d_in[1];   // [4, 2048, 1024]
    float* out = (float*)d_out;               // [4, 2048, 1024]

    void *qhi, *qlo, *vhi, *vlo, *vthi, *vtlo, *phi, *plo, *scores;
    cudaGetSymbolAddress(&qhi, g_qhi);
    cudaGetSymbolAddress(&qlo, g_qlo);
    cudaGetSymbolAddress(&vhi, g_vhi);
    cudaGetSymbolAddress(&vlo, g_vlo);
    cudaGetSymbolAddress(&vthi, g_vthi);
    cudaGetSymbolAddress(&vtlo, g_vtlo);
    cudaGetSymbolAddress(&phi, g_phi);
    cudaGetSymbolAddress(&plo, g_plo);
    cudaGetSymbolAddress(&scores, g_scores);

    cudaFuncSetAttribute(hmma_gemm_kernel,
                         cudaFuncAttributeMaxDynamicSharedMemorySize, SMEM_BYTES);

    // Split Q and V into hi/lo bf16
    {
        int n4 = NB * NQ * ND / 4;
        split_kernel<<<n4 / 256, 256>>>((const float4*)q,
                                        (__nv_bfloat16*)qhi, (__nv_bfloat16*)qlo);
        split_kernel<<<n4 / 256, 256>>>((const float4*)v,
                                        (__nv_bfloat16*)vhi, (__nv_bfloat16*)vlo);
    }
    // V^T split for GEMM2
    {
        dim3 grid(ND / 32, NK / 32, NB);      // (32, 64, 4)
        transpose_split_kernel<<<grid, 256>>>(v, (__nv_bfloat16*)vthi,
                                              (__nv_bfloat16*)vtlo);
    }
    // S = Q @ V^T  (fp32 scores via 3-pass bf16 HMMA)
    {
        dim3 grid(NK / 128, NQ / 128, NB);    // (16, 16, 4)
        hmma_gemm_kernel<<<grid, 256, SMEM_BYTES>>>(
            (const __nv_bfloat16*)qhi, (const __nv_bfloat16*)qlo,
            (const __nv_bfloat16*)vhi, (const __nv_bfloat16*)vlo,
            (float*)scores, ND, NK);
    }
    // P = softmax(S), fused hi/lo split
    {
        softmax_split_kernel<<<NB * NQ, 256>>>((__nv_bfloat16*)phi,
                                               (__nv_bfloat16*)plo);
    }
    // O = P @ V  (B operand = V^T, K-major over seq dim)
    {
        dim3 grid(ND / 128, NQ / 128, NB);    // (8, 16, 4)
        hmma_gemm_kernel<<<grid, 256, SMEM_BYTES>>>(
            (const __nv_bfloat16*)phi, (const __nv_bfloat16*)plo,
            (const __nv_bfloat16*)vthi, (const __nv_bfloat16*)vtlo,
            out, NK, ND);
    }
}

// round 9
// speedup vs baseline: 2.4945x; 1.0340x over previous
#include <cuda_runtime.h>
#include <cuda_bf16.h>
#include <cstdint>
#include <math.h>

// Problem constants
#define NB 4
#define NQ 2048
#define NK 2048
#define ND 1024

// ---------------------------------------------------------------------------
// Device scratch
// ---------------------------------------------------------------------------
__device__ static float g_scores[(size_t)NB * NQ * NK];
__device__ static __nv_bfloat16 g_qhi[(size_t)NB * NQ * ND];
__device__ static __nv_bfloat16 g_qlo[(size_t)NB * NQ * ND];
__device__ static __nv_bfloat16 g_vhi[(size_t)NB * NK * ND];
__device__ static __nv_bfloat16 g_vlo[(size_t)NB * NK * ND];
__device__ static __nv_bfloat16 g_vthi[(size_t)NB * ND * NK];
__device__ static __nv_bfloat16 g_vtlo[(size_t)NB * ND * NK];
__device__ static __nv_bfloat16 g_phi[(size_t)NB * NQ * NK];
__device__ static __nv_bfloat16 g_plo[(size_t)NB * NQ * NK];

// ---------------------------------------------------------------------------
// hi/lo split helpers
// ---------------------------------------------------------------------------
__device__ __forceinline__ void split1(float x, __nv_bfloat16& h, __nv_bfloat16& l) {
    h = __float2bfloat16(x);
    l = __float2bfloat16(x - __bfloat162float(h));
}

__device__ __forceinline__ void split_store4(__nv_bfloat16* hp, __nv_bfloat16* lp, float4 v) {
    __nv_bfloat16 h0, h1, h2, h3, l0, l1, l2, l3;
    split1(v.x, h0, l0); split1(v.y, h1, l1);
    split1(v.z, h2, l2); split1(v.w, h3, l3);
    __nv_bfloat162 ha; ha.x = h0; ha.y = h1;
    __nv_bfloat162 hb; hb.x = h2; hb.y = h3;
    __nv_bfloat162 la; la.x = l0; la.y = l1;
    __nv_bfloat162 lb; lb.x = l2; lb.y = l3;
    *(__nv_bfloat162*)(hp)     = ha;
    *(__nv_bfloat162*)(hp + 2) = hb;
    *(__nv_bfloat162*)(lp)     = la;
    *(__nv_bfloat162*)(lp + 2) = lb;
}

// ---------------------------------------------------------------------------
// Elementwise split: fp32 -> (hi, lo) bf16   (used for Q)
// ---------------------------------------------------------------------------
__global__ __launch_bounds__(256)
void split_kernel(const float4* __restrict__ in, __nv_bfloat16* __restrict__ hi,
                  __nv_bfloat16* __restrict__ lo) {
    int i = blockIdx.x * 256 + threadIdx.x;
    float4 v = in[i];
    split_store4(hi + (size_t)i * 4, lo + (size_t)i * 4, v);
}

// ---------------------------------------------------------------------------
// Fused V split + transpose-split: one read of V produces
//   vhi/vlo [b,k,d]  and  vthi/vtlo [b,d,k]
// ---------------------------------------------------------------------------
__global__ __launch_bounds__(256)
void v_split_transpose_kernel(const float* __restrict__ V,
                              __nv_bfloat16* __restrict__ vhi,
                              __nv_bfloat16* __restrict__ vlo,
                              __nv_bfloat16* __restrict__ vthi,
                              __nv_bfloat16* __restrict__ vtlo) {
    __shared__ float tile[32][33];
    const int b = blockIdx.z;
    const int k0 = blockIdx.y * 32;
    const int d0 = blockIdx.x * 32;
    const int tx = threadIdx.x & 31;
    const int ty = threadIdx.x >> 5;   // 0..7
    const float* Vb = V + (size_t)b * NK * ND;
    __nv_bfloat16* Hr = vhi + (size_t)b * NK * ND;
    __nv_bfloat16* Lr = vlo + (size_t)b * NK * ND;

    #pragma unroll
    for (int r = ty; r < 32; r += 8) {
        float x = Vb[(size_t)(k0 + r) * ND + d0 + tx];
        tile[r][tx] = x;
        __nv_bfloat16 h, l;
        split1(x, h, l);
        size_t o = (size_t)(k0 + r) * ND + d0 + tx;
        Hr[o] = h;
        Lr[o] = l;
    }
    __syncthreads();

    __nv_bfloat16* Ht = vthi + (size_t)b * ND * NK;
    __nv_bfloat16* Lt = vtlo + (size_t)b * ND * NK;
    #pragma unroll
    for (int r = ty; r < 32; r += 8) {
        float x = tile[tx][r];
        __nv_bfloat16 h, l;
        split1(x, h, l);
        size_t o = (size_t)(d0 + r) * NK + k0 + tx;
        Ht[o] = h;
        Lt[o] = l;
    }
}

// ---------------------------------------------------------------------------
// Row softmax over g_scores, fused hi/lo split output.
// ---------------------------------------------------------------------------
__global__ __launch_bounds__(256)
void softmax_split_kernel(__nv_bfloat16* __restrict__ phi,
                          __nv_bfloat16* __restrict__ plo) {
    const size_t row = blockIdx.x;
    float* p = g_scores + row * (size_t)NK;
    float4* p4 = (float4*)p;
    const int tid = threadIdx.x;
    const int lane = tid & 31;
    const int warp = tid >> 5;

    __shared__ float red[8];

    float4 v0 = p4[tid];
    float4 v1 = p4[tid + 256];

    float m = fmaxf(fmaxf(fmaxf(v0.x, v0.y), fmaxf(v0.z, v0.w)),
                    fmaxf(fmaxf(v1.x, v1.y), fmaxf(v1.z, v1.w)));
    #pragma unroll
    for (int off = 16; off > 0; off >>= 1)
        m = fmaxf(m, __shfl_xor_sync(0xffffffffu, m, off));
    if (lane == 0) red[warp] = m;
    __syncthreads();
    float rowmax = red[0];
    #pragma unroll
    for (int w = 1; w < 8; w++) rowmax = fmaxf(rowmax, red[w]);
    __syncthreads();

    v0.x = expf(v0.x - rowmax); v0.y = expf(v0.y - rowmax);
    v0.z = expf(v0.z - rowmax); v0.w = expf(v0.w - rowmax);
    v1.x = expf(v1.x - rowmax); v1.y = expf(v1.y - rowmax);
    v1.z = expf(v1.z - rowmax); v1.w = expf(v1.w - rowmax);

    float s = (v0.x + v0.y + v0.z + v0.w) + (v1.x + v1.y + v1.z + v1.w);
    #pragma unroll
    for (int off = 16; off > 0; off >>= 1)
        s += __shfl_xor_sync(0xffffffffu, s, off);
    if (lane == 0) red[warp] = s;
    __syncthreads();
    float rowsum = 0.0f;
    #pragma unroll
    for (int w = 0; w < 8; w++) rowsum += red[w];

    const float inv = 1.0f / rowsum;
    v0.x *= inv; v0.y *= inv; v0.z *= inv; v0.w *= inv;
    v1.x *= inv; v1.y *= inv; v1.z *= inv; v1.w *= inv;

    __nv_bfloat16* H = phi + row * (size_t)NK;
    __nv_bfloat16* L = plo + row * (size_t)NK;
    split_store4(H + 4 * tid,         L + 4 * tid,         v0);
    split_store4(H + 4 * (tid + 256), L + 4 * (tid + 256), v1);
}

// ---------------------------------------------------------------------------
// HMMA split GEMM, v2:
//   C[b,m,n] = sum_k (Ahi+Alo)[b,m,k] * (Bhi+Blo)[b,n,k]   (hh + hl + lh)
// CTA tile 128x128, K chunk 32, 16 warps (4m x 4n), warp tile 32x32.
// 3-stage cp.async pipeline; ldmatrix.x4 fragment loads.
// ---------------------------------------------------------------------------
#define KCH 32
#define SROW 40                      // padded row stride, bf16 elems (80 B)
#define TILE_E (128 * SROW)          // 5120 elems = 10240 B per operand tile
#define STAGE_E (4 * TILE_E)         // 20480 elems = 40960 B per stage
#define STAGE_B (STAGE_E * 2)
#define NSTAGE 3
#define SMEM_BYTES (NSTAGE * STAGE_B)   // 122880 B

__device__ __forceinline__ void mma_bf16(float* d, const uint32_t* a, const uint32_t* b) {
    asm volatile(
        "mma.sync.aligned.m16n8k16.row.col.f32.bf16.bf16.f32 "
        "{%0,%1,%2,%3}, {%4,%5,%6,%7}, {%8,%9}, {%0,%1,%2,%3};"
        : "+f"(d[0]), "+f"(d[1]), "+f"(d[2]), "+f"(d[3])
        : "r"(a[0]), "r"(a[1]), "r"(a[2]), "r"(a[3]), "r"(b[0]), "r"(b[1]));
}

__device__ __forceinline__ void ldsm_x4(uint32_t* r, uint32_t addr) {
    asm volatile("ldmatrix.sync.aligned.m8n8.x4.shared.b16 {%0,%1,%2,%3}, [%4];"
                 : "=r"(r[0]), "=r"(r[1]), "=r"(r[2]), "=r"(r[3]) : "r"(addr));
}

__device__ __forceinline__ void cp_async16(uint32_t sdst, const void* gsrc) {
    asm volatile("cp.async.cg.shared.global [%0], [%1], 16;" :: "r"(sdst), "l"(gsrc));
}

__device__ __forceinline__ uint32_t smem_u32(const void* p) {
    uint32_t a;
    asm("{ .reg .u64 t; cvta.to.shared.u64 t, %1; cvt.u32.u64 %0, t; }"
        : "=r"(a) : "l"(p));
    return a;
}

__global__ __launch_bounds__(512, 1)
void hmma_gemm_kernel(const __nv_bfloat16* __restrict__ Ahi,
                      const __nv_bfloat16* __restrict__ Alo,
                      const __nv_bfloat16* __restrict__ Bhi,
                      const __nv_bfloat16* __restrict__ Blo,
                      float* __restrict__ C,
                      int Kd, int N) {
    extern __shared__ __nv_bfloat16 sm[];
    const uint32_t smem_base = smem_u32(sm);
    const int tid = threadIdx.x;
    const int wid = tid >> 5;
    const int lane = tid & 31;
    const int group = lane >> 2;
    const int tig = lane & 3;
    const int b = blockIdx.z;
    const int m0 = blockIdx.y * 128;
    const int n0 = blockIdx.x * 128;
    const int wm = (wid & 3) * 32;          // warp m base (4 warps down)
    const int wn = (wid >> 2) * 32;         // warp n base (4 warps across)

    const __nv_bfloat16* srcs[4];
    srcs[0] = Ahi + (size_t)b * 2048 * Kd;
    srcs[1] = Alo + (size_t)b * 2048 * Kd;
    srcs[2] = Bhi + (size_t)b * (size_t)N * Kd;
    srcs[3] = Blo + (size_t)b * (size_t)N * Kd;

    float acc[2][4][4];
    #pragma unroll
    for (int i = 0; i < 2; i++)
        #pragma unroll
        for (int j = 0; j < 4; j++)
            #pragma unroll
            for (int r = 0; r < 4; r++) acc[i][j][r] = 0.0f;

    // Per-thread ldmatrix offsets (bytes within a tile), 16B-aligned rows.
    // A x4: matrices {m-lo/k-lo, m-hi/k-lo, m-lo/k-hi, m-hi/k-hi}
    const int lr = lane & 7;
    const int a_moff = ((lane >> 3) & 1) * 8 + lr;
    const int a_koff = (lane >> 4) * 8;
    // B x4: matrices {n-lo/k-lo, n-lo/k-hi, n-hi/k-lo, n-hi/k-hi}
    const int b_noff = (lane >> 4) * 8 + lr;
    const int b_koff = ((lane >> 3) & 1) * 8;

    uint32_t aoff[2], boff[2];
    #pragma unroll
    for (int mt = 0; mt < 2; ++mt)
        aoff[mt] = (uint32_t)((wm + mt * 16 + a_moff) * (SROW * 2) + a_koff * 2);
    #pragma unroll
    for (int p = 0; p < 2; ++p)
        boff[p] = (uint32_t)((wn + p * 16 + b_noff) * (SROW * 2) + b_koff * 2);

    const int nch = Kd / KCH;

    // --- chunk loader: 2048 x 16B cp.async per CTA, 4 per thread ---
    auto load_chunk = [&](int ci, int stage) {
        const int k0 = ci * KCH;
        const uint32_t sdst0 = smem_base + (uint32_t)stage * STAGE_B;
        #pragma unroll
        for (int j = 0; j < 4; ++j) {
            int idx = tid + j * 512;          // 0..2047
            int T   = idx >> 9;               // operand tile 0..3
            int rem = idx & 511;
            int row = rem >> 2;               // 0..127
            int c   = rem & 3;                // 16B column
            const __nv_bfloat16* src = srcs[T];
            const int r0 = (T < 2) ? m0 : n0;
            cp_async16(sdst0 + (uint32_t)(T * TILE_E + row * SROW + c * 8) * 2,
                       src + (size_t)(r0 + row) * Kd + k0 + c * 8);
        }
        asm volatile("cp.async.commit_group;" ::: "memory");
    };

    load_chunk(0, 0);
    if (nch > 1) load_chunk(1, 1);

    int st = 0;                // stage of chunk i
    int ls = 2 % NSTAGE;       // stage for chunk i+2

    for (int i = 0; i < nch; ++i) {
        if (i < nch - 1)
            asm volatile("cp.async.wait_group 1;" ::: "memory");
        else
            asm volatile("cp.async.wait_group 0;" ::: "memory");
        __syncthreads();

        if (i + 2 < nch) {
            load_chunk(i + 2, ls);
            ls = (ls + 1 == NSTAGE) ? 0 : ls + 1;
        }

        const uint32_t sb  = smem_base + (uint32_t)st * STAGE_B;
        const uint32_t sAh = sb;
        const uint32_t sAl = sb + TILE_E * 2;
        const uint32_t sBh = sb + 2 * TILE_E * 2;
        const uint32_t sBl = sb + 3 * TILE_E * 2;

        uint32_t ah[2][2][4], al[2][2][4], bh[2][2][4], bl[2][2][4];
        #pragma unroll
        for (int ks = 0; ks < 2; ++ks) {
            const uint32_t kadd = (uint32_t)(ks * 32);
            #pragma unroll
            for (int mt = 0; mt < 2; ++mt) {
                ldsm_x4(ah[ks][mt], sAh + aoff[mt] + kadd);
                ldsm_x4(al[ks][mt], sAl + aoff[mt] + kadd);
            }
            #pragma unroll
            for (int p = 0; p < 2; ++p) {
                ldsm_x4(bh[ks][p], sBh + boff[p] + kadd);
                ldsm_x4(bl[ks][p], sBl + boff[p] + kadd);
            }
        }

        #pragma unroll
        for (int ks = 0; ks < 2; ++ks) {
            #pragma unroll
            for (int mt = 0; mt < 2; ++mt) {
                #pragma unroll
                for (int nt = 0; nt < 4; ++nt) {
                    const uint32_t* bhp = &bh[ks][nt >> 1][(nt & 1) * 2];
                    const uint32_t* blp = &bl[ks][nt >> 1][(nt & 1) * 2];
                    mma_bf16(acc[mt][nt], ah[ks][mt], bhp);   // hi*hi
                    mma_bf16(acc[mt][nt], ah[ks][mt], blp);   // hi*lo
                    mma_bf16(acc[mt][nt], al[ks][mt], bhp);   // lo*hi
                }
            }
        }

        st = (st + 1 == NSTAGE) ? 0 : st + 1;
    }

    // Epilogue
    float* Cb = C + (size_t)b * 2048 * (size_t)N;
    #pragma unroll
    for (int mt = 0; mt < 2; ++mt) {
        const int row = m0 + wm + mt * 16 + group;
        #pragma unroll
        for (int nt = 0; nt < 4; ++nt) {
            const int col = n0 + wn + nt * 8 + 2 * tig;
            float2 lo2, hi2;
            lo2.x = acc[mt][nt][0]; lo2.y = acc[mt][nt][1];
            hi2.x = acc[mt][nt][2]; hi2.y = acc[mt][nt][3];
            *(float2*)(Cb + (size_t)row * N + col)       = lo2;
            *(float2*)(Cb + (size_t)(row + 8) * N + col) = hi2;
        }
    }
}

// ---------------------------------------------------------------------------
extern "C" void kernel_launch(void* const* d_in, const int* in_sizes, int n_in,
                              void* d_out, int out_size) {
    const float* q = (const float*)d_in[0];
    const float* v = (const float*)d_in[1];
    float* out = (float*)d_out;

    void *qhi, *qlo, *vhi, *vlo, *vthi, *vtlo, *phi, *plo, *scores;
    cudaGetSymbolAddress(&qhi, g_qhi);
    cudaGetSymbolAddress(&qlo, g_qlo);
    cudaGetSymbolAddress(&vhi, g_vhi);
    cudaGetSymbolAddress(&vlo, g_vlo);
    cudaGetSymbolAddress(&vthi, g_vthi);
    cudaGetSymbolAddress(&vtlo, g_vtlo);
    cudaGetSymbolAddress(&phi, g_phi);
    cudaGetSymbolAddress(&plo, g_plo);
    cudaGetSymbolAddress(&scores, g_scores);

    cudaFuncSetAttribute(hmma_gemm_kernel,
                         cudaFuncAttributeMaxDynamicSharedMemorySize, SMEM_BYTES);

    // Split Q
    {
        int n4 = NB * NQ * ND / 4;
        split_kernel<<<n4 / 256, 256>>>((const float4*)q,
                                        (__nv_bfloat16*)qhi, (__nv_bfloat16*)qlo);
    }
    // Fused V split + transpose-split
    {
        dim3 grid(ND / 32, NK / 32, NB);
        v_split_transpose_kernel<<<grid, 256>>>(v,
            (__nv_bfloat16*)vhi, (__nv_bfloat16*)vlo,
            (__nv_bfloat16*)vthi, (__nv_bfloat16*)vtlo);
    }
    // S = Q @ V^T
    {
        dim3 grid(NK / 128, NQ / 128, NB);    // (16, 16, 4)
        hmma_gemm_kernel<<<grid, 512, SMEM_BYTES>>>(
            (const __nv_bfloat16*)qhi, (const __nv_bfloat16*)qlo,
            (const __nv_bfloat16*)vhi, (const __nv_bfloat16*)vlo,
            (float*)scores, ND, NK);
    }
    // P = softmax(S), fused hi/lo split
    {
        softmax_split_kernel<<<NB * NQ, 256>>>((__nv_bfloat16*)phi,
                                               (__nv_bfloat16*)plo);
    }
    // O = P @ V
    {
        dim3 grid(ND / 128, NQ / 128, NB);    // (8, 16, 4)
        hmma_gemm_kernel<<<grid, 512, SMEM_BYTES>>>(
            (const __nv_bfloat16*)phi, (const __nv_bfloat16*)plo,
            (const __nv_bfloat16*)vthi, (const __nv_bfloat16*)vtlo,
            out, NK, ND);
    }
}

// round 10
// speedup vs baseline: 2.6575x; 1.0653x over previous
#include <cuda_runtime.h>
#include <cuda_bf16.h>
#include <cstdint>
#include <math.h>

// Problem constants
#define NB 4
#define NQ 2048
#define NK 2048
#define ND 1024

// ---------------------------------------------------------------------------
// Device scratch
// ---------------------------------------------------------------------------
__device__ static float g_scores[(size_t)NB * NQ * NK];
__device__ static __nv_bfloat16 g_qhi[(size_t)NB * NQ * ND];
__device__ static __nv_bfloat16 g_qlo[(size_t)NB * NQ * ND];
__device__ static __nv_bfloat16 g_vhi[(size_t)NB * NK * ND];
__device__ static __nv_bfloat16 g_vlo[(size_t)NB * NK * ND];
__device__ static __nv_bfloat16 g_vthi[(size_t)NB * ND * NK];
__device__ static __nv_bfloat16 g_vtlo[(size_t)NB * ND * NK];
__device__ static __nv_bfloat16 g_phi[(size_t)NB * NQ * NK];
__device__ static __nv_bfloat16 g_plo[(size_t)NB * NQ * NK];

// ---------------------------------------------------------------------------
// hi/lo split helpers
// ---------------------------------------------------------------------------
__device__ __forceinline__ void split1(float x, __nv_bfloat16& h, __nv_bfloat16& l) {
    h = __float2bfloat16(x);
    l = __float2bfloat16(x - __bfloat162float(h));
}

__device__ __forceinline__ void split_store4(__nv_bfloat16* hp, __nv_bfloat16* lp, float4 v) {
    __nv_bfloat16 h0, h1, h2, h3, l0, l1, l2, l3;
    split1(v.x, h0, l0); split1(v.y, h1, l1);
    split1(v.z, h2, l2); split1(v.w, h3, l3);
    __nv_bfloat162 ha; ha.x = h0; ha.y = h1;
    __nv_bfloat162 hb; hb.x = h2; hb.y = h3;
    __nv_bfloat162 la; la.x = l0; la.y = l1;
    __nv_bfloat162 lb; lb.x = l2; lb.y = l3;
    *(__nv_bfloat162*)(hp)     = ha;
    *(__nv_bfloat162*)(hp + 2) = hb;
    *(__nv_bfloat162*)(lp)     = la;
    *(__nv_bfloat162*)(lp + 2) = lb;
}

// ---------------------------------------------------------------------------
// Elementwise split (Q)
// ---------------------------------------------------------------------------
__global__ __launch_bounds__(256)
void split_kernel(const float4* __restrict__ in, __nv_bfloat16* __restrict__ hi,
                  __nv_bfloat16* __restrict__ lo) {
    int i = blockIdx.x * 256 + threadIdx.x;
    float4 v = in[i];
    split_store4(hi + (size_t)i * 4, lo + (size_t)i * 4, v);
}

// ---------------------------------------------------------------------------
// Fused V split + transpose-split
// ---------------------------------------------------------------------------
__global__ __launch_bounds__(256)
void v_split_transpose_kernel(const float* __restrict__ V,
                              __nv_bfloat16* __restrict__ vhi,
                              __nv_bfloat16* __restrict__ vlo,
                              __nv_bfloat16* __restrict__ vthi,
                              __nv_bfloat16* __restrict__ vtlo) {
    __shared__ float tile[32][33];
    const int b = blockIdx.z;
    const int k0 = blockIdx.y * 32;
    const int d0 = blockIdx.x * 32;
    const int tx = threadIdx.x & 31;
    const int ty = threadIdx.x >> 5;
    const float* Vb = V + (size_t)b * NK * ND;
    __nv_bfloat16* Hr = vhi + (size_t)b * NK * ND;
    __nv_bfloat16* Lr = vlo + (size_t)b * NK * ND;

    #pragma unroll
    for (int r = ty; r < 32; r += 8) {
        float x = Vb[(size_t)(k0 + r) * ND + d0 + tx];
        tile[r][tx] = x;
        __nv_bfloat16 h, l;
        split1(x, h, l);
        size_t o = (size_t)(k0 + r) * ND + d0 + tx;
        Hr[o] = h;
        Lr[o] = l;
    }
    __syncthreads();

    __nv_bfloat16* Ht = vthi + (size_t)b * ND * NK;
    __nv_bfloat16* Lt = vtlo + (size_t)b * ND * NK;
    #pragma unroll
    for (int r = ty; r < 32; r += 8) {
        float x = tile[tx][r];
        __nv_bfloat16 h, l;
        split1(x, h, l);
        size_t o = (size_t)(d0 + r) * NK + k0 + tx;
        Ht[o] = h;
        Lt[o] = l;
    }
}

// ---------------------------------------------------------------------------
// Row softmax + hi/lo split
// ---------------------------------------------------------------------------
__global__ __launch_bounds__(256)
void softmax_split_kernel(__nv_bfloat16* __restrict__ phi,
                          __nv_bfloat16* __restrict__ plo) {
    const size_t row = blockIdx.x;
    float* p = g_scores + row * (size_t)NK;
    float4* p4 = (float4*)p;
    const int tid = threadIdx.x;
    const int lane = tid & 31;
    const int warp = tid >> 5;

    __shared__ float red[8];

    float4 v0 = p4[tid];
    float4 v1 = p4[tid + 256];

    float m = fmaxf(fmaxf(fmaxf(v0.x, v0.y), fmaxf(v0.z, v0.w)),
                    fmaxf(fmaxf(v1.x, v1.y), fmaxf(v1.z, v1.w)));
    #pragma unroll
    for (int off = 16; off > 0; off >>= 1)
        m = fmaxf(m, __shfl_xor_sync(0xffffffffu, m, off));
    if (lane == 0) red[warp] = m;
    __syncthreads();
    float rowmax = red[0];
    #pragma unroll
    for (int w = 1; w < 8; w++) rowmax = fmaxf(rowmax, red[w]);
    __syncthreads();

    v0.x = expf(v0.x - rowmax); v0.y = expf(v0.y - rowmax);
    v0.z = expf(v0.z - rowmax); v0.w = expf(v0.w - rowmax);
    v1.x = expf(v1.x - rowmax); v1.y = expf(v1.y - rowmax);
    v1.z = expf(v1.z - rowmax); v1.w = expf(v1.w - rowmax);

    float s = (v0.x + v0.y + v0.z + v0.w) + (v1.x + v1.y + v1.z + v1.w);
    #pragma unroll
    for (int off = 16; off > 0; off >>= 1)
        s += __shfl_xor_sync(0xffffffffu, s, off);
    if (lane == 0) red[warp] = s;
    __syncthreads();
    float rowsum = 0.0f;
    #pragma unroll
    for (int w = 0; w < 8; w++) rowsum += red[w];

    const float inv = 1.0f / rowsum;
    v0.x *= inv; v0.y *= inv; v0.z *= inv; v0.w *= inv;
    v1.x *= inv; v1.y *= inv; v1.z *= inv; v1.w *= inv;

    __nv_bfloat16* H = phi + row * (size_t)NK;
    __nv_bfloat16* L = plo + row * (size_t)NK;
    split_store4(H + 4 * tid,         L + 4 * tid,         v0);
    split_store4(H + 4 * (tid + 256), L + 4 * (tid + 256), v1);
}

// ---------------------------------------------------------------------------
// HMMA split GEMM v3 — smem-traffic-minimized:
// CTA tile 128x256, 8 warps (2m x 4n), warp tile 64x64, K chunk 32.
// 2-stage cp.async pipeline; ldmatrix.x4; 3-pass hh+hl+lh, fp32 accum.
// ---------------------------------------------------------------------------
#define KCH 32
#define SROW 40                        // padded row stride (bf16), 80 B
#define SROWB 80
#define ATILE_B (128 * SROWB)          // 10240 B per A operand tile
#define BTILE_B (256 * SROWB)          // 20480 B per B operand tile
#define STAGE_B (2 * ATILE_B + 2 * BTILE_B)   // 61440 B
#define SMEM_BYTES (2 * STAGE_B)               // 122880 B
#define OFF_AH 0
#define OFF_AL ATILE_B
#define OFF_BH (2 * ATILE_B)
#define OFF_BL (2 * ATILE_B + BTILE_B)

__device__ __forceinline__ void mma_bf16(float* d, const uint32_t* a, const uint32_t* b) {
    asm volatile(
        "mma.sync.aligned.m16n8k16.row.col.f32.bf16.bf16.f32 "
        "{%0,%1,%2,%3}, {%4,%5,%6,%7}, {%8,%9}, {%0,%1,%2,%3};"
        : "+f"(d[0]), "+f"(d[1]), "+f"(d[2]), "+f"(d[3])
        : "r"(a[0]), "r"(a[1]), "r"(a[2]), "r"(a[3]), "r"(b[0]), "r"(b[1]));
}

__device__ __forceinline__ void ldsm_x4(uint32_t* r, uint32_t addr) {
    asm volatile("ldmatrix.sync.aligned.m8n8.x4.shared.b16 {%0,%1,%2,%3}, [%4];"
                 : "=r"(r[0]), "=r"(r[1]), "=r"(r[2]), "=r"(r[3]) : "r"(addr));
}

__device__ __forceinline__ void cp_async16(uint32_t sdst, const void* gsrc) {
    asm volatile("cp.async.cg.shared.global [%0], [%1], 16;" :: "r"(sdst), "l"(gsrc));
}

__device__ __forceinline__ uint32_t smem_u32(const void* p) {
    uint32_t a;
    asm("{ .reg .u64 t; cvta.to.shared.u64 t, %1; cvt.u32.u64 %0, t; }"
        : "=r"(a) : "l"(p));
    return a;
}

__global__ __launch_bounds__(256, 1)
void hmma_gemm_kernel(const __nv_bfloat16* __restrict__ Ahi,
                      const __nv_bfloat16* __restrict__ Alo,
                      const __nv_bfloat16* __restrict__ Bhi,
                      const __nv_bfloat16* __restrict__ Blo,
                      float* __restrict__ C,
                      int Kd, int N) {
    extern __shared__ __nv_bfloat16 sm[];
    const uint32_t smem_base = smem_u32(sm);
    const int tid = threadIdx.x;
    const int wid = tid >> 5;
    const int lane = tid & 31;
    const int group = lane >> 2;
    const int tig = lane & 3;
    const int b = blockIdx.z;
    const int m0 = blockIdx.y * 128;
    const int n0 = blockIdx.x * 256;
    const int wm = (wid & 1) * 64;         // warp m base (2 warps down)
    const int wn = (wid >> 1) * 64;        // warp n base (4 warps across)

    const __nv_bfloat16* Asrc[2];
    const __nv_bfloat16* Bsrc[2];
    Asrc[0] = Ahi + (size_t)b * 2048 * Kd;
    Asrc[1] = Alo + (size_t)b * 2048 * Kd;
    Bsrc[0] = Bhi + (size_t)b * (size_t)N * Kd;
    Bsrc[1] = Blo + (size_t)b * (size_t)N * Kd;

    float acc[4][8][4];
    #pragma unroll
    for (int i = 0; i < 4; i++)
        #pragma unroll
        for (int j = 0; j < 8; j++)
            #pragma unroll
            for (int r = 0; r < 4; r++) acc[i][j][r] = 0.0f;

    // ldmatrix per-thread addressing within a 16x16 (rows x bf16-cols) block
    const int lr = lane & 7;
    const int a_moff = ((lane >> 3) & 1) * 8 + lr;
    const int a_koff = (lane >> 4) * 16;           // bytes
    const int b_noff = (lane >> 4) * 8 + lr;
    const int b_koff = ((lane >> 3) & 1) * 16;     // bytes

    uint32_t aoff[4], boff[4];
    #pragma unroll
    for (int mt = 0; mt < 4; ++mt)
        aoff[mt] = (uint32_t)((wm + mt * 16 + a_moff) * SROWB + a_koff);
    #pragma unroll
    for (int p = 0; p < 4; ++p)
        boff[p] = (uint32_t)((wn + p * 16 + b_noff) * SROWB + b_koff);

    const int nch = Kd / KCH;

    // --- chunk loader: 3072 x 16B cp.async per CTA, 12 per thread ---
    auto load_chunk = [&](int ci, int stage) {
        const int k0 = ci * KCH;
        const uint32_t s0 = smem_base + (uint32_t)stage * STAGE_B;
        // A tiles: j = 0..3  (idx 0..1023)
        #pragma unroll
        for (int j = 0; j < 4; ++j) {
            int idx = tid + j * 256;
            int T   = idx >> 9;            // 0..1 (hi, lo)
            int rem = idx & 511;
            int row = rem >> 2;            // 0..127
            int c   = rem & 3;
            cp_async16(s0 + (uint32_t)(T * ATILE_B + row * SROWB + c * 16),
                       Asrc[T] + (size_t)(m0 + row) * Kd + k0 + c * 8);
        }
        // B tiles: j = 0..7  (idx 0..2047)
        #pragma unroll
        for (int j = 0; j < 8; ++j) {
            int idx = tid + j * 256;
            int T   = idx >> 10;           // 0..1 (hi, lo)
            int rem = idx & 1023;
            int row = rem >> 2;            // 0..255
            int c   = rem & 3;
            cp_async16(s0 + (uint32_t)(OFF_BH + T * BTILE_B + row * SROWB + c * 16),
                       Bsrc[T] + (size_t)(n0 + row) * Kd + k0 + c * 8);
        }
        asm volatile("cp.async.commit_group;" ::: "memory");
    };

    load_chunk(0, 0);

    for (int i = 0; i < nch; ++i) {
        if (i + 1 < nch) {
            load_chunk(i + 1, (i + 1) & 1);
            asm volatile("cp.async.wait_group 1;" ::: "memory");
        } else {
            asm volatile("cp.async.wait_group 0;" ::: "memory");
        }
        __syncthreads();

        const uint32_t sb  = smem_base + (uint32_t)(i & 1) * STAGE_B;
        const uint32_t sAh = sb + OFF_AH;
        const uint32_t sAl = sb + OFF_AL;
        const uint32_t sBh = sb + OFF_BH;
        const uint32_t sBl = sb + OFF_BL;

        #pragma unroll
        for (int ks = 0; ks < 2; ++ks) {
            const uint32_t kadd = (uint32_t)(ks * 32);

            uint32_t ah[4][4], al[4][4];
            #pragma unroll
            for (int mt = 0; mt < 4; ++mt) {
                ldsm_x4(ah[mt], sAh + aoff[mt] + kadd);
                ldsm_x4(al[mt], sAl + aoff[mt] + kadd);
            }

            #pragma unroll
            for (int p = 0; p < 4; ++p) {
                uint32_t bhv[4], blv[4];
                ldsm_x4(bhv, sBh + boff[p] + kadd);
                ldsm_x4(blv, sBl + boff[p] + kadd);
                #pragma unroll
                for (int mt = 0; mt < 4; ++mt) {
                    mma_bf16(acc[mt][2 * p],     ah[mt], bhv);       // hi*hi
                    mma_bf16(acc[mt][2 * p],     ah[mt], blv);       // hi*lo
                    mma_bf16(acc[mt][2 * p],     al[mt], bhv);       // lo*hi
                    mma_bf16(acc[mt][2 * p + 1], ah[mt], bhv + 2);
                    mma_bf16(acc[mt][2 * p + 1], ah[mt], blv + 2);
                    mma_bf16(acc[mt][2 * p + 1], al[mt], bhv + 2);
                }
            }
        }
        __syncthreads();
    }

    // Epilogue
    float* Cb = C + (size_t)b * 2048 * (size_t)N;
    #pragma unroll
    for (int mt = 0; mt < 4; ++mt) {
        const int row = m0 + wm + mt * 16 + group;
        #pragma unroll
        for (int nt = 0; nt < 8; ++nt) {
            const int col = n0 + wn + nt * 8 + 2 * tig;
            float2 lo2, hi2;
            lo2.x = acc[mt][nt][0]; lo2.y = acc[mt][nt][1];
            hi2.x = acc[mt][nt][2]; hi2.y = acc[mt][nt][3];
            *(float2*)(Cb + (size_t)row * N + col)       = lo2;
            *(float2*)(Cb + (size_t)(row + 8) * N + col) = hi2;
        }
    }
}

// ---------------------------------------------------------------------------
extern "C" void kernel_launch(void* const* d_in, const int* in_sizes, int n_in,
                              void* d_out, int out_size) {
    const float* q = (const float*)d_in[0];
    const float* v = (const float*)d_in[1];
    float* out = (float*)d_out;

    void *qhi, *qlo, *vhi, *vlo, *vthi, *vtlo, *phi, *plo, *scores;
    cudaGetSymbolAddress(&qhi, g_qhi);
    cudaGetSymbolAddress(&qlo, g_qlo);
    cudaGetSymbolAddress(&vhi, g_vhi);
    cudaGetSymbolAddress(&vlo, g_vlo);
    cudaGetSymbolAddress(&vthi, g_vthi);
    cudaGetSymbolAddress(&vtlo, g_vtlo);
    cudaGetSymbolAddress(&phi, g_phi);
    cudaGetSymbolAddress(&plo, g_plo);
    cudaGetSymbolAddress(&scores, g_scores);

    cudaFuncSetAttribute(hmma_gemm_kernel,
                         cudaFuncAttributeMaxDynamicSharedMemorySize, SMEM_BYTES);

    // Split Q
    {
        int n4 = NB * NQ * ND / 4;
        split_kernel<<<n4 / 256, 256>>>((const float4*)q,
                                        (__nv_bfloat16*)qhi, (__nv_bfloat16*)qlo);
    }
    // Fused V split + transpose-split
    {
        dim3 grid(ND / 32, NK / 32, NB);
        v_split_transpose_kernel<<<grid, 256>>>(v,
            (__nv_bfloat16*)vhi, (__nv_bfloat16*)vlo,
            (__nv_bfloat16*)vthi, (__nv_bfloat16*)vtlo);
    }
    // S = Q @ V^T   (M=2048, N=2048, Kd=1024)
    {
        dim3 grid(NK / 256, NQ / 128, NB);    // (8, 16, 4)
        hmma_gemm_kernel<<<grid, 256, SMEM_BYTES>>>(
            (const __nv_bfloat16*)qhi, (const __nv_bfloat16*)qlo,
            (const __nv_bfloat16*)vhi, (const __nv_bfloat16*)vlo,
            (float*)scores, ND, NK);
    }
    // P = softmax(S), fused hi/lo split
    {
        softmax_split_kernel<<<NB * NQ, 256>>>((__nv_bfloat16*)phi,
                                               (__nv_bfloat16*)plo);
    }
    // O = P @ V   (M=2048, N=1024, Kd=2048)
    {
        dim3 grid(ND / 256, NQ / 128, NB);    // (4, 16, 4)
        hmma_gemm_kernel<<<grid, 256, SMEM_BYTES>>>(
            (const __nv_bfloat16*)phi, (const __nv_bfloat16*)plo,
            (const __nv_bfloat16*)vthi, (const __nv_bfloat16*)vtlo,
            out, NK, ND);
    }
}

// round 12
// speedup vs baseline: 2.6891x; 1.0119x over previous
#include <cuda_runtime.h>
#include <cuda_bf16.h>
#include <cstdint>
#include <math.h>

// Problem constants
#define NB 4
#define NQ 2048
#define NK 2048
#define ND 1024

// ---------------------------------------------------------------------------
// Device scratch
// ---------------------------------------------------------------------------
__device__ static float g_scores[(size_t)NB * NQ * NK];
__device__ static __nv_bfloat16 g_qhi[(size_t)NB * NQ * ND];
__device__ static __nv_bfloat16 g_qlo[(size_t)NB * NQ * ND];
__device__ static __nv_bfloat16 g_vhi[(size_t)NB * NK * ND];
__device__ static __nv_bfloat16 g_vlo[(size_t)NB * NK * ND];
__device__ static __nv_bfloat16 g_vthi[(size_t)NB * ND * NK];
__device__ static __nv_bfloat16 g_vtlo[(size_t)NB * ND * NK];
__device__ static __nv_bfloat16 g_phi[(size_t)NB * NQ * NK];
__device__ static __nv_bfloat16 g_plo[(size_t)NB * NQ * NK];

// ---------------------------------------------------------------------------
// hi/lo split helpers
// ---------------------------------------------------------------------------
__device__ __forceinline__ void split1(float x, __nv_bfloat16& h, __nv_bfloat16& l) {
    h = __float2bfloat16(x);
    l = __float2bfloat16(x - __bfloat162float(h));
}

__device__ __forceinline__ void split_store4(__nv_bfloat16* hp, __nv_bfloat16* lp, float4 v) {
    __nv_bfloat16 h0, h1, h2, h3, l0, l1, l2, l3;
    split1(v.x, h0, l0); split1(v.y, h1, l1);
    split1(v.z, h2, l2); split1(v.w, h3, l3);
    __nv_bfloat162 ha; ha.x = h0; ha.y = h1;
    __nv_bfloat162 hb; hb.x = h2; hb.y = h3;
    __nv_bfloat162 la; la.x = l0; la.y = l1;
    __nv_bfloat162 lb; lb.x = l2; lb.y = l3;
    *(__nv_bfloat162*)(hp)     = ha;
    *(__nv_bfloat162*)(hp + 2) = hb;
    *(__nv_bfloat162*)(lp)     = la;
    *(__nv_bfloat162*)(lp + 2) = lb;
}

// ---------------------------------------------------------------------------
// Elementwise split (Q)
// ---------------------------------------------------------------------------
__global__ __launch_bounds__(256)
void split_kernel(const float4* __restrict__ in, __nv_bfloat16* __restrict__ hi,
                  __nv_bfloat16* __restrict__ lo) {
    int i = blockIdx.x * 256 + threadIdx.x;
    float4 v = in[i];
    split_store4(hi + (size_t)i * 4, lo + (size_t)i * 4, v);
}

// ---------------------------------------------------------------------------
// Fused V split + transpose-split
// ---------------------------------------------------------------------------
__global__ __launch_bounds__(256)
void v_split_transpose_kernel(const float* __restrict__ V,
                              __nv_bfloat16* __restrict__ vhi,
                              __nv_bfloat16* __restrict__ vlo,
                              __nv_bfloat16* __restrict__ vthi,
                              __nv_bfloat16* __restrict__ vtlo) {
    __shared__ float tile[32][33];
    const int b = blockIdx.z;
    const int k0 = blockIdx.y * 32;
    const int d0 = blockIdx.x * 32;
    const int tx = threadIdx.x & 31;
    const int ty = threadIdx.x >> 5;
    const float* Vb = V + (size_t)b * NK * ND;
    __nv_bfloat16* Hr = vhi + (size_t)b * NK * ND;
    __nv_bfloat16* Lr = vlo + (size_t)b * NK * ND;

    #pragma unroll
    for (int r = ty; r < 32; r += 8) {
        float x = Vb[(size_t)(k0 + r) * ND + d0 + tx];
        tile[r][tx] = x;
        __nv_bfloat16 h, l;
        split1(x, h, l);
        size_t o = (size_t)(k0 + r) * ND + d0 + tx;
        Hr[o] = h;
        Lr[o] = l;
    }
    __syncthreads();

    __nv_bfloat16* Ht = vthi + (size_t)b * ND * NK;
    __nv_bfloat16* Lt = vtlo + (size_t)b * ND * NK;
    #pragma unroll
    for (int r = ty; r < 32; r += 8) {
        float x = tile[tx][r];
        __nv_bfloat16 h, l;
        split1(x, h, l);
        size_t o = (size_t)(d0 + r) * NK + k0 + tx;
        Ht[o] = h;
        Lt[o] = l;
    }
}

// ---------------------------------------------------------------------------
// Row softmax + hi/lo split
// ---------------------------------------------------------------------------
__global__ __launch_bounds__(256)
void softmax_split_kernel(__nv_bfloat16* __restrict__ phi,
                          __nv_bfloat16* __restrict__ plo) {
    const size_t row = blockIdx.x;
    float* p = g_scores + row * (size_t)NK;
    float4* p4 = (float4*)p;
    const int tid = threadIdx.x;
    const int lane = tid & 31;
    const int warp = tid >> 5;

    __shared__ float red[8];

    float4 v0 = p4[tid];
    float4 v1 = p4[tid + 256];

    float m = fmaxf(fmaxf(fmaxf(v0.x, v0.y), fmaxf(v0.z, v0.w)),
                    fmaxf(fmaxf(v1.x, v1.y), fmaxf(v1.z, v1.w)));
    #pragma unroll
    for (int off = 16; off > 0; off >>= 1)
        m = fmaxf(m, __shfl_xor_sync(0xffffffffu, m, off));
    if (lane == 0) red[warp] = m;
    __syncthreads();
    float rowmax = red[0];
    #pragma unroll
    for (int w = 1; w < 8; w++) rowmax = fmaxf(rowmax, red[w]);
    __syncthreads();

    v0.x = expf(v0.x - rowmax); v0.y = expf(v0.y - rowmax);
    v0.z = expf(v0.z - rowmax); v0.w = expf(v0.w - rowmax);
    v1.x = expf(v1.x - rowmax); v1.y = expf(v1.y - rowmax);
    v1.z = expf(v1.z - rowmax); v1.w = expf(v1.w - rowmax);

    float s = (v0.x + v0.y + v0.z + v0.w) + (v1.x + v1.y + v1.z + v1.w);
    #pragma unroll
    for (int off = 16; off > 0; off >>= 1)
        s += __shfl_xor_sync(0xffffffffu, s, off);
    if (lane == 0) red[warp] = s;
    __syncthreads();
    float rowsum = 0.0f;
    #pragma unroll
    for (int w = 0; w < 8; w++) rowsum += red[w];

    const float inv = 1.0f / rowsum;
    v0.x *= inv; v0.y *= inv; v0.z *= inv; v0.w *= inv;
    v1.x *= inv; v1.y *= inv; v1.z *= inv; v1.w *= inv;

    __nv_bfloat16* H = phi + row * (size_t)NK;
    __nv_bfloat16* L = plo + row * (size_t)NK;
    split_store4(H + 4 * tid,         L + 4 * tid,         v0);
    split_store4(H + 4 * (tid + 256), L + 4 * (tid + 256), v1);
}

// ---------------------------------------------------------------------------
// HMMA split GEMM v4 — ILP + pipeline fix:
// CTA tile 128x256, 8 warps (2m x 4n), warp tile 64x64, K chunk 32.
// 3-stage cp.async pipeline, ONE __syncthreads per chunk.
// Pass-major MMA ordering: 32 independent MMAs per pass (hh, hl, lh).
// ---------------------------------------------------------------------------
#define KCH 32
#define SROWB 80                       // padded row stride (bytes)
#define ATILE_B (128 * SROWB)          // 10240 B per A operand tile
#define BTILE_B (256 * SROWB)          // 20480 B per B operand tile
#define STAGE_B (2 * ATILE_B + 2 * BTILE_B)   // 61440 B
#define NSTAGE 3
#define SMEM_BYTES (NSTAGE * STAGE_B)          // 184320 B
#define OFF_AH 0
#define OFF_AL ATILE_B
#define OFF_BH (2 * ATILE_B)
#define OFF_BL (2 * ATILE_B + BTILE_B)

__device__ __forceinline__ void mma_bf16(float* d, const uint32_t* a, const uint32_t* b) {
    asm volatile(
        "mma.sync.aligned.m16n8k16.row.col.f32.bf16.bf16.f32 "
        "{%0,%1,%2,%3}, {%4,%5,%6,%7}, {%8,%9}, {%0,%1,%2,%3};"
        : "+f"(d[0]), "+f"(d[1]), "+f"(d[2]), "+f"(d[3])
        : "r"(a[0]), "r"(a[1]), "r"(a[2]), "r"(a[3]), "r"(b[0]), "r"(b[1]));
}

__device__ __forceinline__ void ldsm_x4(uint32_t* r, uint32_t addr) {
    asm volatile("ldmatrix.sync.aligned.m8n8.x4.shared.b16 {%0,%1,%2,%3}, [%4];"
                 : "=r"(r[0]), "=r"(r[1]), "=r"(r[2]), "=r"(r[3]) : "r"(addr));
}

__device__ __forceinline__ void cp_async16(uint32_t sdst, const void* gsrc) {
    asm volatile("cp.async.cg.shared.global [%0], [%1], 16;" :: "r"(sdst), "l"(gsrc));
}

__device__ __forceinline__ uint32_t smem_u32(const void* p) {
    uint32_t a;
    asm("{ .reg .u64 t; cvta.to.shared.u64 t, %1; cvt.u32.u64 %0, t; }"
        : "=r"(a) : "l"(p));
    return a;
}

__global__ __launch_bounds__(256, 1)
void hmma_gemm_kernel(const __nv_bfloat16* __restrict__ Ahi,
                      const __nv_bfloat16* __restrict__ Alo,
                      const __nv_bfloat16* __restrict__ Bhi,
                      const __nv_bfloat16* __restrict__ Blo,
                      float* __restrict__ C,
                      int Kd, int N) {
    extern __shared__ __nv_bfloat16 sm[];
    const uint32_t smem_base = smem_u32(sm);
    const int tid = threadIdx.x;
    const int wid = tid >> 5;
    const int lane = tid & 31;
    const int group = lane >> 2;
    const int tig = lane & 3;
    const int b = blockIdx.z;
    const int m0 = blockIdx.y * 128;
    const int n0 = blockIdx.x * 256;
    const int wm = (wid & 1) * 64;
    const int wn = (wid >> 1) * 64;

    const __nv_bfloat16* Asrc[2];
    const __nv_bfloat16* Bsrc[2];
    Asrc[0] = Ahi + (size_t)b * 2048 * Kd;
    Asrc[1] = Alo + (size_t)b * 2048 * Kd;
    Bsrc[0] = Bhi + (size_t)b * (size_t)N * Kd;
    Bsrc[1] = Blo + (size_t)b * (size_t)N * Kd;

    float acc[4][8][4];
    #pragma unroll
    for (int i = 0; i < 4; i++)
        #pragma unroll
        for (int j = 0; j < 8; j++)
            #pragma unroll
            for (int r = 0; r < 4; r++) acc[i][j][r] = 0.0f;

    // ldmatrix per-thread addressing
    const int lr = lane & 7;
    const int a_moff = ((lane >> 3) & 1) * 8 + lr;
    const int a_koff = (lane >> 4) * 16;           // bytes
    const int b_noff = (lane >> 4) * 8 + lr;
    const int b_koff = ((lane >> 3) & 1) * 16;     // bytes

    uint32_t aoff[4], boff[4];
    #pragma unroll
    for (int mt = 0; mt < 4; ++mt)
        aoff[mt] = (uint32_t)((wm + mt * 16 + a_moff) * SROWB + a_koff);
    #pragma unroll
    for (int p = 0; p < 4; ++p)
        boff[p] = (uint32_t)((wn + p * 16 + b_noff) * SROWB + b_koff);

    const int nch = Kd / KCH;

    // --- chunk loader: 3072 x 16B cp.async per CTA, 12 per thread ---
    auto load_chunk = [&](int ci, int stage) {
        const int k0 = ci * KCH;
        const uint32_t s0 = smem_base + (uint32_t)stage * STAGE_B;
        #pragma unroll
        for (int j = 0; j < 4; ++j) {
            int idx = tid + j * 256;
            int T   = idx >> 9;
            int rem = idx & 511;
            int row = rem >> 2;
            int c   = rem & 3;
            cp_async16(s0 + (uint32_t)(T * ATILE_B + row * SROWB + c * 16),
                       Asrc[T] + (size_t)(m0 + row) * Kd + k0 + c * 8);
        }
        #pragma unroll
        for (int j = 0; j < 8; ++j) {
            int idx = tid + j * 256;
            int T   = idx >> 10;
            int rem = idx & 1023;
            int row = rem >> 2;
            int c   = rem & 3;
            cp_async16(s0 + (uint32_t)(OFF_BH + T * BTILE_B + row * SROWB + c * 16),
                       Bsrc[T] + (size_t)(n0 + row) * Kd + k0 + c * 8);
        }
        asm volatile("cp.async.commit_group;" ::: "memory");
    };

    load_chunk(0, 0);
    if (nch > 1) load_chunk(1, 1);

    int st = 0;                          // stage of chunk being computed
    int ls = 2 % NSTAGE;                 // stage for chunk i+2

    for (int i = 0; i < nch; ++i) {
        if (i + 1 < nch)
            asm volatile("cp.async.wait_group 1;" ::: "memory");
        else
            asm volatile("cp.async.wait_group 0;" ::: "memory");
        __syncthreads();
        // Safe to refill stage (i-1)%3 == (i+2)%3: all warps finished it
        // (compute of chunk i-1 precedes this barrier in program order).
        if (i + 2 < nch) {
            load_chunk(i + 2, ls);
            ls = (ls + 1 == NSTAGE) ? 0 : ls + 1;
        }

        const uint32_t sb  = smem_base + (uint32_t)st * STAGE_B;
        const uint32_t sAh = sb + OFF_AH;
        const uint32_t sAl = sb + OFF_AL;
        const uint32_t sBh = sb + OFF_BH;
        const uint32_t sBl = sb + OFF_BL;

        #pragma unroll
        for (int ks = 0; ks < 2; ++ks) {
            const uint32_t kadd = (uint32_t)(ks * 32);

            uint32_t ah[4][4], al[4][4], bh[4][4], bl[4][4];
            #pragma unroll
            for (int mt = 0; mt < 4; ++mt) {
                ldsm_x4(ah[mt], sAh + aoff[mt] + kadd);
                ldsm_x4(al[mt], sAl + aoff[mt] + kadd);
            }
            #pragma unroll
            for (int p = 0; p < 4; ++p) {
                ldsm_x4(bh[p], sBh + boff[p] + kadd);
                ldsm_x4(bl[p], sBl + boff[p] + kadd);
            }

            // Pass 1: hi*hi  (32 independent MMAs)
            #pragma unroll
            for (int p = 0; p < 4; ++p)
                #pragma unroll
                for (int mt = 0; mt < 4; ++mt) {
                    mma_bf16(acc[mt][2 * p],     ah[mt], &bh[p][0]);
                    mma_bf16(acc[mt][2 * p + 1], ah[mt], &bh[p][2]);
                }
            // Pass 2: hi*lo  (32 independent MMAs)
            #pragma unroll
            for (int p = 0; p < 4; ++p)
                #pragma unroll
                for (int mt = 0; mt < 4; ++mt) {
                    mma_bf16(acc[mt][2 * p],     ah[mt], &bl[p][0]);
                    mma_bf16(acc[mt][2 * p + 1], ah[mt], &bl[p][2]);
                }
            // Pass 3: lo*hi  (32 independent MMAs)
            #pragma unroll
            for (int p = 0; p < 4; ++p)
                #pragma unroll
                for (int mt = 0; mt < 4; ++mt) {
                    mma_bf16(acc[mt][2 * p],     al[mt], &bh[p][0]);
                    mma_bf16(acc[mt][2 * p + 1], al[mt], &bh[p][2]);
                }
        }

        st = (st + 1 == NSTAGE) ? 0 : st + 1;
    }

    // Epilogue
    float* Cb = C + (size_t)b * 2048 * (size_t)N;
    #pragma unroll
    for (int mt = 0; mt < 4; ++mt) {
        const int row = m0 + wm + mt * 16 + group;
        #pragma unroll
        for (int nt = 0; nt < 8; ++nt) {
            const int col = n0 + wn + nt * 8 + 2 * tig;
            float2 lo2, hi2;
            lo2.x = acc[mt][nt][0]; lo2.y = acc[mt][nt][1];
            hi2.x = acc[mt][nt][2]; hi2.y = acc[mt][nt][3];
            *(float2*)(Cb + (size_t)row * N + col)       = lo2;
            *(float2*)(Cb + (size_t)(row + 8) * N + col) = hi2;
        }
    }
}

// ---------------------------------------------------------------------------
extern "C" void kernel_launch(void* const* d_in, const int* in_sizes, int n_in,
                              void* d_out, int out_size) {
    const float* q = (const float*)d_in[0];
    const float* v = (const float*)d_in[1];
    float* out = (float*)d_out;

    void *qhi, *qlo, *vhi, *vlo, *vthi, *vtlo, *phi, *plo, *scores;
    cudaGetSymbolAddress(&qhi, g_qhi);
    cudaGetSymbolAddress(&qlo, g_qlo);
    cudaGetSymbolAddress(&vhi, g_vhi);
    cudaGetSymbolAddress(&vlo, g_vlo);
    cudaGetSymbolAddress(&vthi, g_vthi);
    cudaGetSymbolAddress(&vtlo, g_vtlo);
    cudaGetSymbolAddress(&phi, g_phi);
    cudaGetSymbolAddress(&plo, g_plo);
    cudaGetSymbolAddress(&scores, g_scores);

    cudaFuncSetAttribute(hmma_gemm_kernel,
                         cudaFuncAttributeMaxDynamicSharedMemorySize, SMEM_BYTES);

    // Split Q
    {
        int n4 = NB * NQ * ND / 4;
        split_kernel<<<n4 / 256, 256>>>((const float4*)q,
                                        (__nv_bfloat16*)qhi, (__nv_bfloat16*)qlo);
    }
    // Fused V split + transpose-split
    {
        dim3 grid(ND / 32, NK / 32, NB);
        v_split_transpose_kernel<<<grid, 256>>>(v,
            (__nv_bfloat16*)vhi, (__nv_bfloat16*)vlo,
            (__nv_bfloat16*)vthi, (__nv_bfloat16*)vtlo);
    }
    // S = Q @ V^T   (M=2048, N=2048, Kd=1024)
    {
        dim3 grid(NK / 256, NQ / 128, NB);    // (8, 16, 4)
        hmma_gemm_kernel<<<grid, 256, SMEM_BYTES>>>(
            (const __nv_bfloat16*)qhi, (const __nv_bfloat16*)qlo,
            (const __nv_bfloat16*)vhi, (const __nv_bfloat16*)vlo,
            (float*)scores, ND, NK);
    }
    // P = softmax(S), fused hi/lo split
    {
        softmax_split_kernel<<<NB * NQ, 256>>>((__nv_bfloat16*)phi,
                                               (__nv_bfloat16*)plo);
    }
    // O = P @ V   (M=2048, N=1024, Kd=2048)
    {
        dim3 grid(ND / 256, NQ / 128, NB);    // (4, 16, 4)
        hmma_gemm_kernel<<<grid, 256, SMEM_BYTES>>>(
            (const __nv_bfloat16*)phi, (const __nv_bfloat16*)plo,
            (const __nv_bfloat16*)vthi, (const __nv_bfloat16*)vtlo,
            out, NK, ND);
    }
}